// round 9
// baseline (speedup 1.0000x reference)
#include <cuda_runtime.h>
#include <cuda_fp16.h>
#include <cstdint>

#define N_NODES   50000
#define REL_NUM   16
#define D_IN      64
#define D_OUT     64
#define N_EDGES   1600000

// 102.4 MB fp16 scratch: T[n][r][o], row (n,r) = 64 halfs = 128 B.
__device__ __half g_transformed[(size_t)N_NODES * REL_NUM * D_OUT];

// Counting-sort state for the dst-grouped aggregation.
__device__ int   g_cnt[N_NODES];
__device__ int   g_off[N_NODES];
__device__ int   g_cur[N_NODES];
__device__ int   g_sums[256];
__device__ uint4 g_rec[N_EDGES];   // (src, rel, norm_bits, 0) per edge, dst-sorted

// ---- packed-fp32 helpers -------------------------------------------------
__device__ __forceinline__ unsigned long long splat2(float x) {
    unsigned long long r;
    asm("mov.b64 %0, {%1, %1};" : "=l"(r) : "f"(x));
    return r;
}
__device__ __forceinline__ unsigned long long fma2(unsigned long long a,
                                                   unsigned long long b,
                                                   unsigned long long c) {
    unsigned long long d;
    asm("fma.rn.f32x2 %0, %1, %2, %3;" : "=l"(d) : "l"(a), "l"(b), "l"(c));
    return d;
}
// f32x2 (lo=even col, hi=odd col) -> half2 bits (lo half first)
__device__ __forceinline__ unsigned cvt_f32x2_h2(unsigned long long p) {
    float lo, hi;
    asm("mov.b64 {%0, %1}, %2;" : "=f"(lo), "=f"(hi) : "l"(p));
    unsigned r;
    asm("cvt.rn.f16x2.f32 %0, %1, %2;" : "=r"(r) : "f"(hi), "f"(lo));
    return r;
}
__device__ __forceinline__ unsigned pack_h2(float lo, float hi) {
    unsigned r;
    asm("cvt.rn.f16x2.f32 %0, %1, %2;" : "=r"(r) : "f"(hi), "f"(lo));
    return r;
}

// ---------------------------------------------------------------------------
// Phase 1: T[n, rel, :] = fp16( h[n, :] @ W[rel] )
// 128 threads, tile 128 nodes x 64 cols, 8x8 micro-tile, FFMA2 packed math.
// h tile held in smem as packed fp16 (16 KB) -> one LDS.128 per d for the
// a-operand and 32 KB total smem (7 blocks by smem); launch_bounds(128,5)
// pushes regs <=102 for 20 warps/SM.
// ---------------------------------------------------------------------------
__global__ __launch_bounds__(128, 5)
void transform_kernel(const float* __restrict__ h,
                      const float* __restrict__ W,
                      int n_nodes)
{
    __shared__ __half hsT[D_IN * 128];   // [d][n] fp16, row = 128 halfs = 256 B
    __shared__ float  Ws [D_IN * D_OUT]; // [d][chunk-permuted cols] fp32

    const int rel = blockIdx.y;
    const int n0  = blockIdx.x * 128;
    const int tid = threadIdx.x;

    // --- Load W[rel] with chunk permutation p(c) = (c>>1) | ((c&1)<<3) ---
    {
        const float* Wr  = W + (size_t)rel * D_IN * D_OUT;
        float4*      Ws4 = reinterpret_cast<float4*>(Ws);
        #pragma unroll
        for (int i = tid; i < (D_IN * D_OUT) / 4; i += 128) {
            const int d = i >> 4;
            const int c = i & 15;
            const int p = (c >> 1) | ((c & 1) << 3);
            // smem is [d][n] K-as-rows? No: Ws[d*64 + col] with cols permuted by
            // 4-wide chunk. Gather W[d][c*4 .. c*4+3] (row-major, contiguous).
            const float4 v = *reinterpret_cast<const float4*>(Wr + d * D_OUT + c * 4);
            Ws4[d * 16 + p] = v;
        }
    }

    // --- Load h tile, 4x4 register transpose, pack node-pairs to fp16 ---
    {
        const int nb = tid & 31;   // node quad: nodes nb*4 .. nb*4+3
        const int dq = tid >> 5;   // 0..3
        #pragma unroll
        for (int kk = 0; kk < 4; kk++) {
            const int d4 = (dq + kk * 4) * 4;   // dims d4 .. d4+3
            float hv[4][4];
            #pragma unroll
            for (int k = 0; k < 4; k++) {
                const int n = n0 + nb * 4 + k;
                float4 v = make_float4(0.f, 0.f, 0.f, 0.f);
                if (n < n_nodes)
                    v = *reinterpret_cast<const float4*>(h + (size_t)n * D_IN + d4);
                hv[k][0] = v.x; hv[k][1] = v.y; hv[k][2] = v.z; hv[k][3] = v.w;
            }
            #pragma unroll
            for (int j = 0; j < 4; j++) {
                uint2 st;
                st.x = pack_h2(hv[0][j], hv[1][j]);   // nodes nb*4+0, +1
                st.y = pack_h2(hv[2][j], hv[3][j]);   // nodes nb*4+2, +3
                *reinterpret_cast<uint2*>(&hsT[(d4 + j) * 128 + nb * 4]) = st;
            }
        }
    }
    __syncthreads();

    const int cg = tid & 7;    // cols cg*8 .. cg*8+7
    const int ng = tid >> 3;   // nodes ng*8 .. ng*8+7

    unsigned long long acc[8][4];
    #pragma unroll
    for (int i = 0; i < 8; i++)
        #pragma unroll
        for (int j = 0; j < 4; j++) acc[i][j] = 0ull;

    const ulonglong2* Wsu = reinterpret_cast<const ulonglong2*>(Ws); // [64][16 chunks]

    #pragma unroll 8
    for (int d = 0; d < D_IN; d++) {
        // a: 8 nodes' dim-d values, one LDS.128 (8 halfs).
        const uint4 av = *reinterpret_cast<const uint4*>(&hsT[d * 128 + ng * 8]);
        const float2 a01 = __half22float2(*reinterpret_cast<const __half2*>(&av.x));
        const float2 a23 = __half22float2(*reinterpret_cast<const __half2*>(&av.y));
        const float2 a45 = __half22float2(*reinterpret_cast<const __half2*>(&av.z));
        const float2 a67 = __half22float2(*reinterpret_cast<const __half2*>(&av.w));
        // b: logical chunks 2cg, 2cg+1 at permuted positions cg, cg+8.
        const ulonglong2 b0 = Wsu[d * 16 + cg];
        const ulonglong2 b1 = Wsu[d * 16 + cg + 8];

        #define ROW(i, ax)                                   \
        {                                                    \
            const unsigned long long aa = splat2(ax);        \
            acc[i][0] = fma2(aa, b0.x, acc[i][0]);           \
            acc[i][1] = fma2(aa, b0.y, acc[i][1]);           \
            acc[i][2] = fma2(aa, b1.x, acc[i][2]);           \
            acc[i][3] = fma2(aa, b1.y, acc[i][3]);           \
        }
        ROW(0, a01.x) ROW(1, a01.y) ROW(2, a23.x) ROW(3, a23.y)
        ROW(4, a45.x) ROW(5, a45.y) ROW(6, a67.x) ROW(7, a67.y)
        #undef ROW
    }

    // Epilogue: fp16 rows, 16 B per node-row segment.
    #pragma unroll
    for (int i = 0; i < 8; i++) {
        const int n = n0 + ng * 8 + i;
        if (n < n_nodes) {
            uint4 o;
            o.x = cvt_f32x2_h2(acc[i][0]);
            o.y = cvt_f32x2_h2(acc[i][1]);
            o.z = cvt_f32x2_h2(acc[i][2]);
            o.w = cvt_f32x2_h2(acc[i][3]);
            __half* p = g_transformed + ((size_t)n * REL_NUM + rel) * D_OUT + cg * 8;
            *reinterpret_cast<uint4*>(p) = o;
        }
    }
}

// ---------------------------------------------------------------------------
// Phase 2a: counting sort of edges by dst.
// ---------------------------------------------------------------------------
__global__ __launch_bounds__(256)
void zero_kernel()
{
    const int i = blockIdx.x * 256 + threadIdx.x;
    if (i < N_NODES) g_cnt[i] = 0;
    if (i < 256)     g_sums[i] = 0;
}

__global__ __launch_bounds__(256)
void hist_kernel(const int* __restrict__ dst, long long n_edges)
{
    const long long e = (long long)blockIdx.x * 256 + threadIdx.x;
    if (e < n_edges) atomicAdd(&g_cnt[dst[e]], 1);
}

__device__ __forceinline__ int block_incl_scan(int* s, int t, int c)
{
    s[t] = c;
    __syncthreads();
    #pragma unroll
    for (int off = 1; off < 256; off <<= 1) {
        const int v = (t >= off) ? s[t - off] : 0;
        __syncthreads();
        s[t] += v;
        __syncthreads();
    }
    return s[t];
}

__global__ __launch_bounds__(256)
void chunk_scan_kernel(int n_bins)
{
    __shared__ int s[256];
    const int t   = threadIdx.x;
    const int bin = blockIdx.x * 256 + t;
    const int c   = (bin < n_bins) ? g_cnt[bin] : 0;
    const int inc = block_incl_scan(s, t, c);
    if (bin < n_bins) g_off[bin] = inc - c;     // exclusive within chunk
    if (t == 255)     g_sums[blockIdx.x] = s[255];
}

__global__ void scan_sums_kernel()
{
    __shared__ int s[256];
    const int t = threadIdx.x;
    const int c = g_sums[t];
    const int inc = block_incl_scan(s, t, c);
    g_sums[t] = inc - c;                        // exclusive across chunks
}

__global__ __launch_bounds__(256)
void finalize_kernel(int n_bins)
{
    const int bin = blockIdx.x * 256 + threadIdx.x;
    if (bin < n_bins) {
        const int o = g_off[bin] + g_sums[blockIdx.x];
        g_off[bin] = o;
        g_cur[bin] = o;
    }
}

__global__ __launch_bounds__(256)
void scatter_rec_kernel(const float* __restrict__ norm,
                        const int*   __restrict__ src,
                        const int*   __restrict__ dst,
                        const int*   __restrict__ rel,
                        long long n_edges)
{
    const long long e = (long long)blockIdx.x * 256 + threadIdx.x;
    if (e >= n_edges) return;
    const int t   = dst[e];
    const int pos = atomicAdd(&g_cur[t], 1);
    g_rec[pos] = make_uint4((unsigned)src[e], (unsigned)rel[e],
                            __float_as_uint(norm[e]), 0u);
}

// ---------------------------------------------------------------------------
// Phase 2b: warp-per-node aggregation. No atomics: each warp owns one dst
// node, accumulates its edge segment in fp32 registers (2 cols/lane), applies
// ReLU, and writes the final 256 B row. Covers every node (zeros included),
// so no out memset is needed.
// ---------------------------------------------------------------------------
__global__ __launch_bounds__(256)
void aggregate_kernel(float* __restrict__ out, int n_nodes)
{
    const int v   = blockIdx.x * 8 + (threadIdx.x >> 5);
    const int lid = threadIdx.x & 31;
    if (v >= n_nodes) return;

    const int beg = g_off[v];
    const int cnt = g_cnt[v];

    float ax = 0.f, ay = 0.f;
    int i = 0;
    for (; i + 2 <= cnt; i += 2) {
        const uint4 r0 = g_rec[beg + i];
        const uint4 r1 = g_rec[beg + i + 1];
        const __half2 h0 = *reinterpret_cast<const __half2*>(
            g_transformed + (((size_t)r0.x * REL_NUM + r0.y) << 6) + 2 * lid);
        const __half2 h1 = *reinterpret_cast<const __half2*>(
            g_transformed + (((size_t)r1.x * REL_NUM + r1.y) << 6) + 2 * lid);
        const float n0 = __uint_as_float(r0.z);
        const float n1 = __uint_as_float(r1.z);
        const float2 f0 = __half22float2(h0);
        const float2 f1 = __half22float2(h1);
        ax = fmaf(n0, f0.x, ax); ay = fmaf(n0, f0.y, ay);
        ax = fmaf(n1, f1.x, ax); ay = fmaf(n1, f1.y, ay);
    }
    if (i < cnt) {
        const uint4 r0 = g_rec[beg + i];
        const __half2 h0 = *reinterpret_cast<const __half2*>(
            g_transformed + (((size_t)r0.x * REL_NUM + r0.y) << 6) + 2 * lid);
        const float n0 = __uint_as_float(r0.z);
        const float2 f0 = __half22float2(h0);
        ax = fmaf(n0, f0.x, ax); ay = fmaf(n0, f0.y, ay);
    }

    float2 st;
    st.x = fmaxf(ax, 0.f);
    st.y = fmaxf(ay, 0.f);
    *reinterpret_cast<float2*>(out + (size_t)v * D_OUT + 2 * lid) = st;
}

extern "C" void kernel_launch(void* const* d_in, const int* in_sizes, int n_in,
                              void* d_out, int out_size)
{
    // metadata order: h, weight, norm, src, dst, rel_type
    const float* h    = (const float*)d_in[0];
    const float* W    = (const float*)d_in[1];
    const float* norm = (const float*)d_in[2];
    const int*   src  = (const int*)d_in[3];
    const int*   dst  = (const int*)d_in[4];
    const int*   rel  = (const int*)d_in[5];
    float*       out  = (float*)d_out;

    const int       n_nodes = in_sizes[0] / D_IN;   // 50000
    const long long n_edges = in_sizes[3];          // 1,600,000
    const int       nchunks = (n_nodes + 255) / 256;
    const int       eblocks = (int)((n_edges + 255) / 256);

    // Phase 1: per-(node, relation) transform (FFMA2, fp16 smem A, fp16 scratch).
    {
        dim3 grid((n_nodes + 127) / 128, REL_NUM);
        transform_kernel<<<grid, 128>>>(h, W, n_nodes);
    }

    // Phase 2a: counting sort of edges by dst.
    zero_kernel<<<nchunks, 256>>>();
    hist_kernel<<<eblocks, 256>>>(dst, n_edges);
    chunk_scan_kernel<<<nchunks, 256>>>(n_nodes);
    scan_sums_kernel<<<1, 256>>>();
    finalize_kernel<<<nchunks, 256>>>(n_nodes);
    scatter_rec_kernel<<<eblocks, 256>>>(norm, src, dst, rel, n_edges);

    // Phase 2b: atomic-free aggregation + ReLU + store (writes every node).
    aggregate_kernel<<<(n_nodes + 7) / 8, 256>>>(out, n_nodes);
}

// round 11
// speedup vs baseline: 1.1540x; 1.1540x over previous
#include <cuda_runtime.h>
#include <cuda_fp16.h>
#include <cstdint>

#define N_NODES   50000
#define REL_NUM   16
#define D_IN      64
#define D_OUT     64
#define N_EDGES   1600000

// 102.4 MB fp16 scratch: T[n][r][o], row (n,r) = 64 halfs = 128 B.
// Row index == key = (n << 4) | r.
__device__ __half g_transformed[(size_t)N_NODES * REL_NUM * D_OUT];

// Counting-sort state for the dst-grouped aggregation.
__device__ int   g_cnt[N_NODES];
__device__ int   g_off[N_NODES];
__device__ int   g_cur[N_NODES];
__device__ int   g_sums[256];
__device__ uint2 g_rec[N_EDGES];   // (key = src*16+rel, norm_bits), dst-sorted

// ---- packed-fp32 helpers -------------------------------------------------
__device__ __forceinline__ unsigned long long splat2(float x) {
    unsigned long long r;
    asm("mov.b64 %0, {%1, %1};" : "=l"(r) : "f"(x));
    return r;
}
__device__ __forceinline__ unsigned long long fma2(unsigned long long a,
                                                   unsigned long long b,
                                                   unsigned long long c) {
    unsigned long long d;
    asm("fma.rn.f32x2 %0, %1, %2, %3;" : "=l"(d) : "l"(a), "l"(b), "l"(c));
    return d;
}
// f32x2 (lo=even col, hi=odd col) -> half2 bits (lo half first)
__device__ __forceinline__ unsigned cvt_f32x2_h2(unsigned long long p) {
    float lo, hi;
    asm("mov.b64 {%0, %1}, %2;" : "=f"(lo), "=f"(hi) : "l"(p));
    unsigned r;
    asm("cvt.rn.f16x2.f32 %0, %1, %2;" : "=r"(r) : "f"(hi), "f"(lo));
    return r;
}

// ---------------------------------------------------------------------------
// Phase 1: T[n, rel, :] = fp16( h[n, :] @ W[rel] )   -- exact R5 version
// (measured 159us): 128 threads, 128 nodes x 64 cols, 8x8 micro-tile, FFMA2.
// ---------------------------------------------------------------------------
__global__ __launch_bounds__(128)
void transform_kernel(const float* __restrict__ h,
                      const float* __restrict__ W,
                      int n_nodes)
{
    __shared__ float hsT[D_IN * 128];   // [d][n] fp32
    __shared__ float Ws [D_IN * D_OUT]; // [d][chunk-permuted cols]

    const int rel = blockIdx.y;
    const int n0  = blockIdx.x * 128;
    const int tid = threadIdx.x;

    // --- Load W[rel] with chunk permutation p(c) = (c>>1) | ((c&1)<<3) ---
    {
        const float4* Wg  = reinterpret_cast<const float4*>(W + (size_t)rel * D_IN * D_OUT);
        float4*       Ws4 = reinterpret_cast<float4*>(Ws);
        #pragma unroll
        for (int i = tid; i < (D_IN * D_OUT) / 4; i += 128) {
            const int d = i >> 4;
            const int c = i & 15;
            const int p = (c >> 1) | ((c & 1) << 3);
            Ws4[d * 16 + p] = Wg[i];
        }
    }

    // --- Load h tile with 4x4 register transpose -> hsT[d][n] ---
    {
        float4* hsT4 = reinterpret_cast<float4*>(hsT);
        const int nb = tid & 31;   // node quad
        const int dq = tid >> 5;   // 0..3
        #pragma unroll
        for (int kk = 0; kk < 4; kk++) {
            const int d4 = (dq + kk * 4) * 4;
            float hv[4][4];
            #pragma unroll
            for (int k = 0; k < 4; k++) {
                const int n = n0 + nb * 4 + k;
                float4 v = make_float4(0.f, 0.f, 0.f, 0.f);
                if (n < n_nodes)
                    v = *reinterpret_cast<const float4*>(h + (size_t)n * D_IN + d4);
                hv[k][0] = v.x; hv[k][1] = v.y; hv[k][2] = v.z; hv[k][3] = v.w;
            }
            #pragma unroll
            for (int j = 0; j < 4; j++) {
                float4 w = make_float4(hv[0][j], hv[1][j], hv[2][j], hv[3][j]);
                hsT4[(d4 + j) * 32 + nb] = w;
            }
        }
    }
    __syncthreads();

    const int cg = tid & 7;    // cols cg*8 .. cg*8+7
    const int ng = tid >> 3;   // nodes ng*8 .. ng*8+7

    unsigned long long acc[8][4];
    #pragma unroll
    for (int i = 0; i < 8; i++)
        #pragma unroll
        for (int j = 0; j < 4; j++) acc[i][j] = 0ull;

    const float4*     hsT4 = reinterpret_cast<const float4*>(hsT);
    const ulonglong2* Wsu  = reinterpret_cast<const ulonglong2*>(Ws);

    #pragma unroll 8
    for (int d = 0; d < D_IN; d++) {
        const float4 a0 = hsT4[d * 32 + ng * 2];
        const float4 a1 = hsT4[d * 32 + ng * 2 + 1];
        const ulonglong2 b0 = Wsu[d * 16 + cg];
        const ulonglong2 b1 = Wsu[d * 16 + cg + 8];

        float a[8] = {a0.x, a0.y, a0.z, a0.w, a1.x, a1.y, a1.z, a1.w};
        #pragma unroll
        for (int i = 0; i < 8; i++) {
            const unsigned long long aa = splat2(a[i]);
            acc[i][0] = fma2(aa, b0.x, acc[i][0]);
            acc[i][1] = fma2(aa, b0.y, acc[i][1]);
            acc[i][2] = fma2(aa, b1.x, acc[i][2]);
            acc[i][3] = fma2(aa, b1.y, acc[i][3]);
        }
    }

    #pragma unroll
    for (int i = 0; i < 8; i++) {
        const int n = n0 + ng * 8 + i;
        if (n < n_nodes) {
            uint4 o;
            o.x = cvt_f32x2_h2(acc[i][0]);
            o.y = cvt_f32x2_h2(acc[i][1]);
            o.z = cvt_f32x2_h2(acc[i][2]);
            o.w = cvt_f32x2_h2(acc[i][3]);
            __half* p = g_transformed + ((size_t)n * REL_NUM + rel) * D_OUT + cg * 8;
            *reinterpret_cast<uint4*>(p) = o;
        }
    }
}

// ---------------------------------------------------------------------------
// Phase 2a: counting sort of edges by dst.
// ---------------------------------------------------------------------------
__global__ __launch_bounds__(256)
void zero_kernel()
{
    const int i = blockIdx.x * 256 + threadIdx.x;
    if (i < N_NODES) g_cnt[i] = 0;
    if (i < 256)     g_sums[i] = 0;
}

__global__ __launch_bounds__(256)
void hist_kernel(const int* __restrict__ dst, long long n_edges)
{
    const long long e = (long long)blockIdx.x * 256 + threadIdx.x;
    if (e < n_edges) atomicAdd(&g_cnt[dst[e]], 1);
}

__device__ __forceinline__ int block_incl_scan(int* s, int t, int c)
{
    s[t] = c;
    __syncthreads();
    #pragma unroll
    for (int off = 1; off < 256; off <<= 1) {
        const int v = (t >= off) ? s[t - off] : 0;
        __syncthreads();
        s[t] += v;
        __syncthreads();
    }
    return s[t];
}

__global__ __launch_bounds__(256)
void chunk_scan_kernel(int n_bins)
{
    __shared__ int s[256];
    const int t   = threadIdx.x;
    const int bin = blockIdx.x * 256 + t;
    const int c   = (bin < n_bins) ? g_cnt[bin] : 0;
    const int inc = block_incl_scan(s, t, c);
    if (bin < n_bins) g_off[bin] = inc - c;
    if (t == 255)     g_sums[blockIdx.x] = s[255];
}

__global__ void scan_sums_kernel()
{
    __shared__ int s[256];
    const int t = threadIdx.x;
    const int c = g_sums[t];
    const int inc = block_incl_scan(s, t, c);
    g_sums[t] = inc - c;
}

__global__ __launch_bounds__(256)
void finalize_kernel(int n_bins)
{
    const int bin = blockIdx.x * 256 + threadIdx.x;
    if (bin < n_bins) {
        const int o = g_off[bin] + g_sums[blockIdx.x];
        g_off[bin] = o;
        g_cur[bin] = o;
    }
}

__global__ __launch_bounds__(256)
void scatter_rec_kernel(const float* __restrict__ norm,
                        const int*   __restrict__ src,
                        const int*   __restrict__ dst,
                        const int*   __restrict__ rel,
                        long long n_edges)
{
    const long long e = (long long)blockIdx.x * 256 + threadIdx.x;
    if (e >= n_edges) return;
    const int t   = dst[e];
    const int pos = atomicAdd(&g_cur[t], 1);
    g_rec[pos] = make_uint2(((unsigned)src[e] << 4) | (unsigned)rel[e],
                            __float_as_uint(norm[e]));
}

// ---------------------------------------------------------------------------
// Phase 2b: warp-per-node aggregation, atomic-free. Each lane owns 2 cols;
// each edge-row gather is a fully-coalesced 128 B warp read. Unroll x4 for
// memory-level parallelism. Fuses norm scale, ReLU, final store; writes every
// node so no output memset needed.
// ---------------------------------------------------------------------------
__global__ __launch_bounds__(256)
void aggregate_kernel(float* __restrict__ out, int n_nodes)
{
    const int v   = blockIdx.x * 8 + (threadIdx.x >> 5);
    const int lid = threadIdx.x & 31;
    if (v >= n_nodes) return;

    const int beg = g_off[v];
    const int end = beg + g_cnt[v];

    float ax = 0.f, ay = 0.f;
    int i = beg;
    for (; i + 4 <= end; i += 4) {
        const uint2 r0 = g_rec[i + 0];
        const uint2 r1 = g_rec[i + 1];
        const uint2 r2 = g_rec[i + 2];
        const uint2 r3 = g_rec[i + 3];
        const __half2 h0 = reinterpret_cast<const __half2*>(
            g_transformed + ((size_t)r0.x << 6))[lid];
        const __half2 h1 = reinterpret_cast<const __half2*>(
            g_transformed + ((size_t)r1.x << 6))[lid];
        const __half2 h2 = reinterpret_cast<const __half2*>(
            g_transformed + ((size_t)r2.x << 6))[lid];
        const __half2 h3 = reinterpret_cast<const __half2*>(
            g_transformed + ((size_t)r3.x << 6))[lid];
        const float2 f0 = __half22float2(h0);
        const float2 f1 = __half22float2(h1);
        const float2 f2 = __half22float2(h2);
        const float2 f3 = __half22float2(h3);
        const float n0 = __uint_as_float(r0.y);
        const float n1 = __uint_as_float(r1.y);
        const float n2 = __uint_as_float(r2.y);
        const float n3 = __uint_as_float(r3.y);
        ax = fmaf(n0, f0.x, ax); ay = fmaf(n0, f0.y, ay);
        ax = fmaf(n1, f1.x, ax); ay = fmaf(n1, f1.y, ay);
        ax = fmaf(n2, f2.x, ax); ay = fmaf(n2, f2.y, ay);
        ax = fmaf(n3, f3.x, ax); ay = fmaf(n3, f3.y, ay);
    }
    for (; i < end; i++) {
        const uint2 r0 = g_rec[i];
        const __half2 h0 = reinterpret_cast<const __half2*>(
            g_transformed + ((size_t)r0.x << 6))[lid];
        const float2 f0 = __half22float2(h0);
        const float n0 = __uint_as_float(r0.y);
        ax = fmaf(n0, f0.x, ax); ay = fmaf(n0, f0.y, ay);
    }

    float2 st;
    st.x = fmaxf(ax, 0.f);
    st.y = fmaxf(ay, 0.f);
    *reinterpret_cast<float2*>(out + (size_t)v * D_OUT + 2 * lid) = st;
}

extern "C" void kernel_launch(void* const* d_in, const int* in_sizes, int n_in,
                              void* d_out, int out_size)
{
    // metadata order: h, weight, norm, src, dst, rel_type
    const float* h    = (const float*)d_in[0];
    const float* W    = (const float*)d_in[1];
    const float* norm = (const float*)d_in[2];
    const int*   src  = (const int*)d_in[3];
    const int*   dst  = (const int*)d_in[4];
    const int*   rel  = (const int*)d_in[5];
    float*       out  = (float*)d_out;

    const int       n_nodes = in_sizes[0] / D_IN;   // 50000
    const long long n_edges = in_sizes[3];          // 1,600,000
    const int       nchunks = (n_nodes + 255) / 256;
    const int       eblocks = (int)((n_edges + 255) / 256);

    // Phase 1: per-(node, relation) transform (R5 config, measured 159us).
    {
        dim3 grid((n_nodes + 127) / 128, REL_NUM);
        transform_kernel<<<grid, 128>>>(h, W, n_nodes);
    }

    // Phase 2a: counting sort of edges by dst (8-byte records).
    zero_kernel<<<nchunks, 256>>>();
    hist_kernel<<<eblocks, 256>>>(dst, n_edges);
    chunk_scan_kernel<<<nchunks, 256>>>(n_nodes);
    scan_sums_kernel<<<1, 256>>>();
    finalize_kernel<<<nchunks, 256>>>(n_nodes);
    scatter_rec_kernel<<<eblocks, 256>>>(norm, src, dst, rel, n_edges);

    // Phase 2b: atomic-free aggregation + ReLU + store.
    aggregate_kernel<<<(n_nodes + 7) / 8, 256>>>(out, n_nodes);
}

// round 12
// speedup vs baseline: 1.1755x; 1.0186x over previous
#include <cuda_runtime.h>
#include <cuda_fp16.h>
#include <cstdint>

#define N_NODES   50000
#define REL_NUM   16
#define D_IN      64
#define D_OUT     64
#define N_EDGES   1600000

// 102.4 MB fp16 scratch: T[n][r][o], row (n,r) = 64 halfs = 128 B.
// Row index == key = (n << 4) | r.
__device__ __half g_transformed[(size_t)N_NODES * REL_NUM * D_OUT];

// Counting-sort state for the dst-grouped aggregation.
__device__ int   g_cnt[N_NODES];
__device__ int   g_off[N_NODES];
__device__ int   g_cur[N_NODES];
__device__ int   g_sums[256];
__device__ uint2 g_rec[N_EDGES];   // (key = src*16+rel, norm_bits), dst-sorted

// ---- packed-fp32 helpers -------------------------------------------------
__device__ __forceinline__ unsigned long long splat2(float x) {
    unsigned long long r;
    asm("mov.b64 %0, {%1, %1};" : "=l"(r) : "f"(x));
    return r;
}
__device__ __forceinline__ unsigned long long fma2(unsigned long long a,
                                                   unsigned long long b,
                                                   unsigned long long c) {
    unsigned long long d;
    asm("fma.rn.f32x2 %0, %1, %2, %3;" : "=l"(d) : "l"(a), "l"(b), "l"(c));
    return d;
}
__device__ __forceinline__ unsigned cvt_f32x2_h2(unsigned long long p) {
    float lo, hi;
    asm("mov.b64 {%0, %1}, %2;" : "=f"(lo), "=f"(hi) : "l"(p));
    unsigned r;
    asm("cvt.rn.f16x2.f32 %0, %1, %2;" : "=r"(r) : "f"(hi), "f"(lo));
    return r;
}

// ---------------------------------------------------------------------------
// Phase 1: T[n, rel, :] = fp16( h[n, :] @ W[rel] )   -- R11-passing version,
// byte-identical (measured 159us standalone).
// ---------------------------------------------------------------------------
__global__ __launch_bounds__(128)
void transform_kernel(const float* __restrict__ h,
                      const float* __restrict__ W,
                      int n_nodes)
{
    __shared__ float hsT[D_IN * 128];   // [d][n] fp32
    __shared__ float Ws [D_IN * D_OUT]; // [d][chunk-permuted cols]

    const int rel = blockIdx.y;
    const int n0  = blockIdx.x * 128;
    const int tid = threadIdx.x;

    {
        const float4* Wg  = reinterpret_cast<const float4*>(W + (size_t)rel * D_IN * D_OUT);
        float4*       Ws4 = reinterpret_cast<float4*>(Ws);
        #pragma unroll
        for (int i = tid; i < (D_IN * D_OUT) / 4; i += 128) {
            const int d = i >> 4;
            const int c = i & 15;
            const int p = (c >> 1) | ((c & 1) << 3);
            Ws4[d * 16 + p] = Wg[i];
        }
    }

    {
        float4* hsT4 = reinterpret_cast<float4*>(hsT);
        const int nb = tid & 31;
        const int dq = tid >> 5;
        #pragma unroll
        for (int kk = 0; kk < 4; kk++) {
            const int d4 = (dq + kk * 4) * 4;
            float hv[4][4];
            #pragma unroll
            for (int k = 0; k < 4; k++) {
                const int n = n0 + nb * 4 + k;
                float4 v = make_float4(0.f, 0.f, 0.f, 0.f);
                if (n < n_nodes)
                    v = *reinterpret_cast<const float4*>(h + (size_t)n * D_IN + d4);
                hv[k][0] = v.x; hv[k][1] = v.y; hv[k][2] = v.z; hv[k][3] = v.w;
            }
            #pragma unroll
            for (int j = 0; j < 4; j++) {
                float4 w = make_float4(hv[0][j], hv[1][j], hv[2][j], hv[3][j]);
                hsT4[(d4 + j) * 32 + nb] = w;
            }
        }
    }
    __syncthreads();

    const int cg = tid & 7;
    const int ng = tid >> 3;

    unsigned long long acc[8][4];
    #pragma unroll
    for (int i = 0; i < 8; i++)
        #pragma unroll
        for (int j = 0; j < 4; j++) acc[i][j] = 0ull;

    const float4*     hsT4 = reinterpret_cast<const float4*>(hsT);
    const ulonglong2* Wsu  = reinterpret_cast<const ulonglong2*>(Ws);

    #pragma unroll 8
    for (int d = 0; d < D_IN; d++) {
        const float4 a0 = hsT4[d * 32 + ng * 2];
        const float4 a1 = hsT4[d * 32 + ng * 2 + 1];
        const ulonglong2 b0 = Wsu[d * 16 + cg];
        const ulonglong2 b1 = Wsu[d * 16 + cg + 8];

        float a[8] = {a0.x, a0.y, a0.z, a0.w, a1.x, a1.y, a1.z, a1.w};
        #pragma unroll
        for (int i = 0; i < 8; i++) {
            const unsigned long long aa = splat2(a[i]);
            acc[i][0] = fma2(aa, b0.x, acc[i][0]);
            acc[i][1] = fma2(aa, b0.y, acc[i][1]);
            acc[i][2] = fma2(aa, b1.x, acc[i][2]);
            acc[i][3] = fma2(aa, b1.y, acc[i][3]);
        }
    }

    #pragma unroll
    for (int i = 0; i < 8; i++) {
        const int n = n0 + ng * 8 + i;
        if (n < n_nodes) {
            uint4 o;
            o.x = cvt_f32x2_h2(acc[i][0]);
            o.y = cvt_f32x2_h2(acc[i][1]);
            o.z = cvt_f32x2_h2(acc[i][2]);
            o.w = cvt_f32x2_h2(acc[i][3]);
            __half* p = g_transformed + ((size_t)n * REL_NUM + rel) * D_OUT + cg * 8;
            *reinterpret_cast<uint4*>(p) = o;
        }
    }
}

// ---------------------------------------------------------------------------
// Phase 2a: counting sort of edges by dst (runs on side stream, concurrent
// with the transform -- no data dependency between them).
// ---------------------------------------------------------------------------
__global__ __launch_bounds__(256)
void zero_kernel()
{
    const int i = blockIdx.x * 256 + threadIdx.x;
    if (i < N_NODES) g_cnt[i] = 0;
    if (i < 256)     g_sums[i] = 0;
}

__global__ __launch_bounds__(256)
void hist_kernel(const int* __restrict__ dst, int n_edges)
{
    const int e4 = (blockIdx.x * 256 + threadIdx.x) * 4;
    if (e4 + 4 <= n_edges) {
        const int4 d4 = *reinterpret_cast<const int4*>(dst + e4);
        atomicAdd(&g_cnt[d4.x], 1);
        atomicAdd(&g_cnt[d4.y], 1);
        atomicAdd(&g_cnt[d4.z], 1);
        atomicAdd(&g_cnt[d4.w], 1);
    } else {
        for (int e = e4; e < n_edges; e++) atomicAdd(&g_cnt[dst[e]], 1);
    }
}

__device__ __forceinline__ int block_incl_scan(int* s, int t, int c)
{
    s[t] = c;
    __syncthreads();
    #pragma unroll
    for (int off = 1; off < 256; off <<= 1) {
        const int v = (t >= off) ? s[t - off] : 0;
        __syncthreads();
        s[t] += v;
        __syncthreads();
    }
    return s[t];
}

__global__ __launch_bounds__(256)
void chunk_scan_kernel(int n_bins)
{
    __shared__ int s[256];
    const int t   = threadIdx.x;
    const int bin = blockIdx.x * 256 + t;
    const int c   = (bin < n_bins) ? g_cnt[bin] : 0;
    const int inc = block_incl_scan(s, t, c);
    if (bin < n_bins) g_off[bin] = inc - c;
    if (t == 255)     g_sums[blockIdx.x] = s[255];
}

__global__ void scan_sums_kernel()
{
    __shared__ int s[256];
    const int t = threadIdx.x;
    const int c = g_sums[t];
    const int inc = block_incl_scan(s, t, c);
    g_sums[t] = inc - c;
}

__global__ __launch_bounds__(256)
void finalize_kernel(int n_bins)
{
    const int bin = blockIdx.x * 256 + threadIdx.x;
    if (bin < n_bins) {
        const int o = g_off[bin] + g_sums[blockIdx.x];
        g_off[bin] = o;
        g_cur[bin] = o;
    }
}

__global__ __launch_bounds__(256)
void scatter_rec_kernel(const float* __restrict__ norm,
                        const int*   __restrict__ src,
                        const int*   __restrict__ dst,
                        const int*   __restrict__ rel,
                        int n_edges)
{
    const int e4 = (blockIdx.x * 256 + threadIdx.x) * 4;
    if (e4 + 4 <= n_edges) {
        const int4   s4 = *reinterpret_cast<const int4*>(src + e4);
        const int4   d4 = *reinterpret_cast<const int4*>(dst + e4);
        const int4   r4 = *reinterpret_cast<const int4*>(rel + e4);
        const float4 n4 = *reinterpret_cast<const float4*>(norm + e4);
        int p0 = atomicAdd(&g_cur[d4.x], 1);
        g_rec[p0] = make_uint2(((unsigned)s4.x << 4) | (unsigned)r4.x, __float_as_uint(n4.x));
        int p1 = atomicAdd(&g_cur[d4.y], 1);
        g_rec[p1] = make_uint2(((unsigned)s4.y << 4) | (unsigned)r4.y, __float_as_uint(n4.y));
        int p2 = atomicAdd(&g_cur[d4.z], 1);
        g_rec[p2] = make_uint2(((unsigned)s4.z << 4) | (unsigned)r4.z, __float_as_uint(n4.z));
        int p3 = atomicAdd(&g_cur[d4.w], 1);
        g_rec[p3] = make_uint2(((unsigned)s4.w << 4) | (unsigned)r4.w, __float_as_uint(n4.w));
    } else {
        for (int e = e4; e < n_edges; e++) {
            const int pos = atomicAdd(&g_cur[dst[e]], 1);
            g_rec[pos] = make_uint2(((unsigned)src[e] << 4) | (unsigned)rel[e],
                                    __float_as_uint(norm[e]));
        }
    }
}

// ---------------------------------------------------------------------------
// Phase 2b: warp-per-node aggregation (R11-passing version, unchanged).
// ---------------------------------------------------------------------------
__global__ __launch_bounds__(256)
void aggregate_kernel(float* __restrict__ out, int n_nodes)
{
    const int v   = blockIdx.x * 8 + (threadIdx.x >> 5);
    const int lid = threadIdx.x & 31;
    if (v >= n_nodes) return;

    const int beg = g_off[v];
    const int end = beg + g_cnt[v];

    float ax = 0.f, ay = 0.f;
    int i = beg;
    for (; i + 4 <= end; i += 4) {
        const uint2 r0 = g_rec[i + 0];
        const uint2 r1 = g_rec[i + 1];
        const uint2 r2 = g_rec[i + 2];
        const uint2 r3 = g_rec[i + 3];
        const __half2 h0 = reinterpret_cast<const __half2*>(
            g_transformed + ((size_t)r0.x << 6))[lid];
        const __half2 h1 = reinterpret_cast<const __half2*>(
            g_transformed + ((size_t)r1.x << 6))[lid];
        const __half2 h2 = reinterpret_cast<const __half2*>(
            g_transformed + ((size_t)r2.x << 6))[lid];
        const __half2 h3 = reinterpret_cast<const __half2*>(
            g_transformed + ((size_t)r3.x << 6))[lid];
        const float2 f0 = __half22float2(h0);
        const float2 f1 = __half22float2(h1);
        const float2 f2 = __half22float2(h2);
        const float2 f3 = __half22float2(h3);
        const float n0 = __uint_as_float(r0.y);
        const float n1 = __uint_as_float(r1.y);
        const float n2 = __uint_as_float(r2.y);
        const float n3 = __uint_as_float(r3.y);
        ax = fmaf(n0, f0.x, ax); ay = fmaf(n0, f0.y, ay);
        ax = fmaf(n1, f1.x, ax); ay = fmaf(n1, f1.y, ay);
        ax = fmaf(n2, f2.x, ax); ay = fmaf(n2, f2.y, ay);
        ax = fmaf(n3, f3.x, ax); ay = fmaf(n3, f3.y, ay);
    }
    for (; i < end; i++) {
        const uint2 r0 = g_rec[i];
        const __half2 h0 = reinterpret_cast<const __half2*>(
            g_transformed + ((size_t)r0.x << 6))[lid];
        const float2 f0 = __half22float2(h0);
        const float n0 = __uint_as_float(r0.y);
        ax = fmaf(n0, f0.x, ax); ay = fmaf(n0, f0.y, ay);
    }

    float2 st;
    st.x = fmaxf(ax, 0.f);
    st.y = fmaxf(ay, 0.f);
    *reinterpret_cast<float2*>(out + (size_t)v * D_OUT + 2 * lid) = st;
}

extern "C" void kernel_launch(void* const* d_in, const int* in_sizes, int n_in,
                              void* d_out, int out_size)
{
    // metadata order: h, weight, norm, src, dst, rel_type
    const float* h    = (const float*)d_in[0];
    const float* W    = (const float*)d_in[1];
    const float* norm = (const float*)d_in[2];
    const int*   src  = (const int*)d_in[3];
    const int*   dst  = (const int*)d_in[4];
    const int*   rel  = (const int*)d_in[5];
    float*       out  = (float*)d_out;

    const int n_nodes = in_sizes[0] / D_IN;   // 50000
    const int n_edges = in_sizes[3];          // 1,600,000
    const int nchunks = (n_nodes + 255) / 256;
    const int eblk4   = (n_edges / 4 + 255) / 256;

    // One-time side-stream + fork/join events. Created on the first call,
    // which the harness runs uncaptured; later captured calls only USE them
    // (the documented multi-stream capture pattern). Work per call identical.
    static cudaStream_t s2 = nullptr;
    static cudaEvent_t  ev_fork = nullptr, ev_join = nullptr;
    if (s2 == nullptr) {
        cudaStreamCreateWithFlags(&s2, cudaStreamNonBlocking);
        cudaEventCreateWithFlags(&ev_fork, cudaEventDisableTiming);
        cudaEventCreateWithFlags(&ev_join, cudaEventDisableTiming);
    }

    // Fork: side stream branch starts now.
    cudaEventRecord(ev_fork, 0);
    cudaStreamWaitEvent(s2, ev_fork, 0);

    // Branch A (stream 0): dense transform (FMA-bound, DRAM 4.6% -> the
    // memory-light sort branch hides underneath it).
    {
        dim3 grid((n_nodes + 127) / 128, REL_NUM);
        transform_kernel<<<grid, 128>>>(h, W, n_nodes);
    }

    // Branch B (stream s2): counting sort of edges by dst.
    zero_kernel<<<nchunks, 256, 0, s2>>>();
    hist_kernel<<<eblk4, 256, 0, s2>>>(dst, n_edges);
    chunk_scan_kernel<<<nchunks, 256, 0, s2>>>(n_nodes);
    scan_sums_kernel<<<1, 256, 0, s2>>>();
    finalize_kernel<<<nchunks, 256, 0, s2>>>(n_nodes);
    scatter_rec_kernel<<<eblk4, 256, 0, s2>>>(norm, src, dst, rel, n_edges);
    cudaEventRecord(ev_join, s2);

    // Join: aggregation needs both the scratch (A) and sorted records (B).
    cudaStreamWaitEvent(0, ev_join, 0);
    aggregate_kernel<<<(n_nodes + 7) / 8, 256>>>(out, n_nodes);
}

// round 13
// speedup vs baseline: 1.2492x; 1.0627x over previous
#include <cuda_runtime.h>
#include <cuda_fp16.h>
#include <cstdint>

#define N_NODES   50000
#define REL_NUM   16
#define D_IN      64
#define D_OUT     64
#define N_EDGES   1600000
#define K_HALF    32

// 102.4 MB fp16 scratch: T[n][r][o], row (n,r) = 64 halfs = 128 B.
// Row index == key = (n << 4) | r.
__device__ __half g_transformed[(size_t)N_NODES * REL_NUM * D_OUT];

// Counting-sort state for the dst-grouped aggregation.
__device__ int   g_cnt[N_NODES];
__device__ int   g_off[N_NODES];
__device__ int   g_cur[N_NODES];
__device__ int   g_sums[256];
__device__ uint2 g_rec[N_EDGES];   // (key = src*16+rel, norm_bits), dst-sorted

// ---- packed-fp32 helpers -------------------------------------------------
__device__ __forceinline__ unsigned long long splat2(float x) {
    unsigned long long r;
    asm("mov.b64 %0, {%1, %1};" : "=l"(r) : "f"(x));
    return r;
}
__device__ __forceinline__ unsigned long long fma2(unsigned long long a,
                                                   unsigned long long b,
                                                   unsigned long long c) {
    unsigned long long d;
    asm("fma.rn.f32x2 %0, %1, %2, %3;" : "=l"(d) : "l"(a), "l"(b), "l"(c));
    return d;
}
__device__ __forceinline__ unsigned cvt_f32x2_h2(unsigned long long p) {
    float lo, hi;
    asm("mov.b64 {%0, %1}, %2;" : "=f"(lo), "=f"(hi) : "l"(p));
    unsigned r;
    asm("cvt.rn.f16x2.f32 %0, %1, %2;" : "=r"(r) : "f"(hi), "f"(lo));
    return r;
}

// ---------------------------------------------------------------------------
// Phase 1: T[n, rel, :] = fp16( h[n, :] @ W[rel] )
// K-split variant: hsT holds 32 of 64 input dims per pass -> 16 KB + 16 KB Ws
// = 32 KB/block -> 7 blocks/SM (was 4 at 48 KB). Inner loop identical fp32
// FFMA2 8x8 micro-tile; accumulators persist across the two K passes.
// ---------------------------------------------------------------------------
__global__ __launch_bounds__(128)
void transform_kernel(const float* __restrict__ h,
                      const float* __restrict__ W,
                      int n_nodes)
{
    __shared__ float hsT[K_HALF * 128];  // [d_local][n] fp32, 16 KB
    __shared__ float Ws [D_IN * D_OUT];  // [d][chunk-permuted cols], 16 KB

    const int rel = blockIdx.y;
    const int n0  = blockIdx.x * 128;
    const int tid = threadIdx.x;

    // --- Load W[rel] with chunk permutation p(c) = (c>>1) | ((c&1)<<3) ---
    {
        const float4* Wg  = reinterpret_cast<const float4*>(W + (size_t)rel * D_IN * D_OUT);
        float4*       Ws4 = reinterpret_cast<float4*>(Ws);
        #pragma unroll
        for (int i = tid; i < (D_IN * D_OUT) / 4; i += 128) {
            const int d = i >> 4;
            const int c = i & 15;
            const int p = (c >> 1) | ((c & 1) << 3);
            Ws4[d * 16 + p] = Wg[i];
        }
    }

    const int cg = tid & 7;    // cols cg*8 .. cg*8+7
    const int ng = tid >> 3;   // nodes ng*8 .. ng*8+7

    unsigned long long acc[8][4];
    #pragma unroll
    for (int i = 0; i < 8; i++)
        #pragma unroll
        for (int j = 0; j < 4; j++) acc[i][j] = 0ull;

    const float4*     hsT4c = reinterpret_cast<const float4*>(hsT);
    const ulonglong2* Wsu   = reinterpret_cast<const ulonglong2*>(Ws);

    #pragma unroll
    for (int pass = 0; pass < 2; pass++) {
        if (pass) __syncthreads();   // compute(pass-1) done before hsT reuse

        // --- Load h dims [pass*32, pass*32+32) with 4x4 register transpose ---
        {
            float4* hsT4 = reinterpret_cast<float4*>(hsT);
            const int nb = tid & 31;   // node quad
            const int dq = tid >> 5;   // 0..3
            #pragma unroll
            for (int kk = 0; kk < 2; kk++) {
                const int dl = (dq + kk * 4) * 4;       // local dim base 0..28
                const int d4 = pass * K_HALF + dl;      // global dim base
                float hv[4][4];
                #pragma unroll
                for (int k = 0; k < 4; k++) {
                    const int n = n0 + nb * 4 + k;
                    float4 v = make_float4(0.f, 0.f, 0.f, 0.f);
                    if (n < n_nodes)
                        v = *reinterpret_cast<const float4*>(h + (size_t)n * D_IN + d4);
                    hv[k][0] = v.x; hv[k][1] = v.y; hv[k][2] = v.z; hv[k][3] = v.w;
                }
                #pragma unroll
                for (int j = 0; j < 4; j++) {
                    float4 w = make_float4(hv[0][j], hv[1][j], hv[2][j], hv[3][j]);
                    hsT4[(dl + j) * 32 + nb] = w;
                }
            }
        }
        __syncthreads();   // hsT (and, on pass 0, Ws) visible

        #pragma unroll 8
        for (int d = 0; d < K_HALF; d++) {
            const float4 a0 = hsT4c[d * 32 + ng * 2];
            const float4 a1 = hsT4c[d * 32 + ng * 2 + 1];
            const int dg = pass * K_HALF + d;
            const ulonglong2 b0 = Wsu[dg * 16 + cg];
            const ulonglong2 b1 = Wsu[dg * 16 + cg + 8];

            float a[8] = {a0.x, a0.y, a0.z, a0.w, a1.x, a1.y, a1.z, a1.w};
            #pragma unroll
            for (int i = 0; i < 8; i++) {
                const unsigned long long aa = splat2(a[i]);
                acc[i][0] = fma2(aa, b0.x, acc[i][0]);
                acc[i][1] = fma2(aa, b0.y, acc[i][1]);
                acc[i][2] = fma2(aa, b1.x, acc[i][2]);
                acc[i][3] = fma2(aa, b1.y, acc[i][3]);
            }
        }
    }

    // Epilogue: fp16 rows, 16 B per node-row segment.
    #pragma unroll
    for (int i = 0; i < 8; i++) {
        const int n = n0 + ng * 8 + i;
        if (n < n_nodes) {
            uint4 o;
            o.x = cvt_f32x2_h2(acc[i][0]);
            o.y = cvt_f32x2_h2(acc[i][1]);
            o.z = cvt_f32x2_h2(acc[i][2]);
            o.w = cvt_f32x2_h2(acc[i][3]);
            __half* p = g_transformed + ((size_t)n * REL_NUM + rel) * D_OUT + cg * 8;
            *reinterpret_cast<uint4*>(p) = o;
        }
    }
}

// ---------------------------------------------------------------------------
// Phase 2a: counting sort of edges by dst (side stream, overlaps transform).
// ---------------------------------------------------------------------------
__global__ __launch_bounds__(256)
void zero_kernel()
{
    const int i = blockIdx.x * 256 + threadIdx.x;
    if (i < N_NODES) g_cnt[i] = 0;
    if (i < 256)     g_sums[i] = 0;
}

__global__ __launch_bounds__(256)
void hist_kernel(const int* __restrict__ dst, int n_edges)
{
    const int e4 = (blockIdx.x * 256 + threadIdx.x) * 4;
    if (e4 + 4 <= n_edges) {
        const int4 d4 = *reinterpret_cast<const int4*>(dst + e4);
        atomicAdd(&g_cnt[d4.x], 1);
        atomicAdd(&g_cnt[d4.y], 1);
        atomicAdd(&g_cnt[d4.z], 1);
        atomicAdd(&g_cnt[d4.w], 1);
    } else {
        for (int e = e4; e < n_edges; e++) atomicAdd(&g_cnt[dst[e]], 1);
    }
}

__device__ __forceinline__ int block_incl_scan(int* s, int t, int c)
{
    s[t] = c;
    __syncthreads();
    #pragma unroll
    for (int off = 1; off < 256; off <<= 1) {
        const int v = (t >= off) ? s[t - off] : 0;
        __syncthreads();
        s[t] += v;
        __syncthreads();
    }
    return s[t];
}

__global__ __launch_bounds__(256)
void chunk_scan_kernel(int n_bins)
{
    __shared__ int s[256];
    const int t   = threadIdx.x;
    const int bin = blockIdx.x * 256 + t;
    const int c   = (bin < n_bins) ? g_cnt[bin] : 0;
    const int inc = block_incl_scan(s, t, c);
    if (bin < n_bins) g_off[bin] = inc - c;
    if (t == 255)     g_sums[blockIdx.x] = s[255];
}

__global__ void scan_sums_kernel()
{
    __shared__ int s[256];
    const int t = threadIdx.x;
    const int c = g_sums[t];
    const int inc = block_incl_scan(s, t, c);
    g_sums[t] = inc - c;
}

__global__ __launch_bounds__(256)
void finalize_kernel(int n_bins)
{
    const int bin = blockIdx.x * 256 + threadIdx.x;
    if (bin < n_bins) {
        const int o = g_off[bin] + g_sums[blockIdx.x];
        g_off[bin] = o;
        g_cur[bin] = o;
    }
}

__global__ __launch_bounds__(256)
void scatter_rec_kernel(const float* __restrict__ norm,
                        const int*   __restrict__ src,
                        const int*   __restrict__ dst,
                        const int*   __restrict__ rel,
                        int n_edges)
{
    const int e4 = (blockIdx.x * 256 + threadIdx.x) * 4;
    if (e4 + 4 <= n_edges) {
        const int4   s4 = *reinterpret_cast<const int4*>(src + e4);
        const int4   d4 = *reinterpret_cast<const int4*>(dst + e4);
        const int4   r4 = *reinterpret_cast<const int4*>(rel + e4);
        const float4 n4 = *reinterpret_cast<const float4*>(norm + e4);
        int p0 = atomicAdd(&g_cur[d4.x], 1);
        g_rec[p0] = make_uint2(((unsigned)s4.x << 4) | (unsigned)r4.x, __float_as_uint(n4.x));
        int p1 = atomicAdd(&g_cur[d4.y], 1);
        g_rec[p1] = make_uint2(((unsigned)s4.y << 4) | (unsigned)r4.y, __float_as_uint(n4.y));
        int p2 = atomicAdd(&g_cur[d4.z], 1);
        g_rec[p2] = make_uint2(((unsigned)s4.z << 4) | (unsigned)r4.z, __float_as_uint(n4.z));
        int p3 = atomicAdd(&g_cur[d4.w], 1);
        g_rec[p3] = make_uint2(((unsigned)s4.w << 4) | (unsigned)r4.w, __float_as_uint(n4.w));
    } else {
        for (int e = e4; e < n_edges; e++) {
            const int pos = atomicAdd(&g_cur[dst[e]], 1);
            g_rec[pos] = make_uint2(((unsigned)src[e] << 4) | (unsigned)rel[e],
                                    __float_as_uint(norm[e]));
        }
    }
}

// ---------------------------------------------------------------------------
// Phase 2b: warp-per-node aggregation, atomic-free. Unroll x8 with all record
// loads hoisted ahead of the gathers -> 8 outstanding 128 B row gathers per
// warp for latency hiding. Fuses norm scale + ReLU + final store.
// ---------------------------------------------------------------------------
__global__ __launch_bounds__(256)
void aggregate_kernel(float* __restrict__ out, int n_nodes)
{
    const int v   = blockIdx.x * 8 + (threadIdx.x >> 5);
    const int lid = threadIdx.x & 31;
    if (v >= n_nodes) return;

    const int beg = g_off[v];
    const int end = beg + g_cnt[v];

    float ax = 0.f, ay = 0.f;
    int i = beg;
    for (; i + 8 <= end; i += 8) {
        uint2 r[8];
        #pragma unroll
        for (int u = 0; u < 8; u++) r[u] = g_rec[i + u];
        __half2 hh[8];
        #pragma unroll
        for (int u = 0; u < 8; u++)
            hh[u] = reinterpret_cast<const __half2*>(
                g_transformed + ((size_t)r[u].x << 6))[lid];
        #pragma unroll
        for (int u = 0; u < 8; u++) {
            const float2 f = __half22float2(hh[u]);
            const float  nm = __uint_as_float(r[u].y);
            ax = fmaf(nm, f.x, ax);
            ay = fmaf(nm, f.y, ay);
        }
    }
    for (; i < end; i++) {
        const uint2 r0 = g_rec[i];
        const __half2 h0 = reinterpret_cast<const __half2*>(
            g_transformed + ((size_t)r0.x << 6))[lid];
        const float2 f0 = __half22float2(h0);
        const float n0 = __uint_as_float(r0.y);
        ax = fmaf(n0, f0.x, ax); ay = fmaf(n0, f0.y, ay);
    }

    float2 st;
    st.x = fmaxf(ax, 0.f);
    st.y = fmaxf(ay, 0.f);
    *reinterpret_cast<float2*>(out + (size_t)v * D_OUT + 2 * lid) = st;
}

extern "C" void kernel_launch(void* const* d_in, const int* in_sizes, int n_in,
                              void* d_out, int out_size)
{
    // metadata order: h, weight, norm, src, dst, rel_type
    const float* h    = (const float*)d_in[0];
    const float* W    = (const float*)d_in[1];
    const float* norm = (const float*)d_in[2];
    const int*   src  = (const int*)d_in[3];
    const int*   dst  = (const int*)d_in[4];
    const int*   rel  = (const int*)d_in[5];
    float*       out  = (float*)d_out;

    const int n_nodes = in_sizes[0] / D_IN;   // 50000
    const int n_edges = in_sizes[3];          // 1,600,000
    const int nchunks = (n_nodes + 255) / 256;
    const int eblk4   = (n_edges / 4 + 255) / 256;

    // One-time side-stream + fork/join events (created on the uncaptured
    // first call; captured calls only use them — standard multi-stream
    // capture pattern; identical work every call).
    static cudaStream_t s2 = nullptr;
    static cudaEvent_t  ev_fork = nullptr, ev_join = nullptr;
    if (s2 == nullptr) {
        cudaStreamCreateWithFlags(&s2, cudaStreamNonBlocking);
        cudaEventCreateWithFlags(&ev_fork, cudaEventDisableTiming);
        cudaEventCreateWithFlags(&ev_join, cudaEventDisableTiming);
    }

    cudaEventRecord(ev_fork, 0);
    cudaStreamWaitEvent(s2, ev_fork, 0);

    // Branch A (stream 0): dense transform.
    {
        dim3 grid((n_nodes + 127) / 128, REL_NUM);
        transform_kernel<<<grid, 128>>>(h, W, n_nodes);
    }

    // Branch B (stream s2): counting sort of edges by dst.
    zero_kernel<<<nchunks, 256, 0, s2>>>();
    hist_kernel<<<eblk4, 256, 0, s2>>>(dst, n_edges);
    chunk_scan_kernel<<<nchunks, 256, 0, s2>>>(n_nodes);
    scan_sums_kernel<<<1, 256, 0, s2>>>();
    finalize_kernel<<<nchunks, 256, 0, s2>>>(n_nodes);
    scatter_rec_kernel<<<eblk4, 256, 0, s2>>>(norm, src, dst, rel, n_edges);
    cudaEventRecord(ev_join, s2);

    // Join: aggregation needs both the scratch (A) and sorted records (B).
    cudaStreamWaitEvent(0, ev_join, 0);
    aggregate_kernel<<<(n_nodes + 7) / 8, 256>>>(out, n_nodes);
}